// round 2
// baseline (speedup 1.0000x reference)
#include <cuda_runtime.h>
#include <math.h>

#define B_ 4
#define S_ 8192
#define D_ 1024
#define H_ 8
#define DK_ 64
#define DV_ 64
#define DH_ 4096
#define FULL_ 2048
#define SEG_ 256
#define NFULL_ 4
#define T_ 1024           // selected tokens per batch
#define TT_ 4096          // total selected tokens
#define HD_ 512           // H*DK = H*DV

// ---------------- scratch (static device globals; no allocation) -------------
__device__ float g_xsel[TT_ * D_];
__device__ float g_q[TT_ * HD_];
__device__ float g_k[TT_ * HD_];
__device__ float g_v[TT_ * HD_];
__device__ float g_att[TT_ * HD_];
__device__ float g_a[TT_ * D_];
__device__ float g_h1[(size_t)TT_ * DH_];
__device__ float g_h[TT_ * D_];
__device__ float g_mem[B_ * H_ * DK_ * DV_];
__device__ float g_z[B_ * H_ * DK_];
__device__ int   g_sel[TT_];
__device__ int   g_inv[B_ * S_];

__device__ __forceinline__ float elup1(float x) {
    // elu(x) + 1:  x>0 -> x+1 ; else exp(x)
    return x > 0.f ? x + 1.f : __expf(x);
}

// ---------------- scores: s = x @ w_sample + b ; also init g_inv = -1 --------
__global__ void scores_kernel(const float* __restrict__ x,
                              const float* __restrict__ w,
                              const float* __restrict__ bsm,
                              float* __restrict__ out_scores,
                              int* __restrict__ inv) {
    __shared__ float ws[D_];
    int tid = threadIdx.x;
    for (int e = tid; e < D_; e += 256) ws[e] = w[e];
    __syncthreads();
    int lane = tid & 31, wrp = tid >> 5;
    int tok = blockIdx.x * 8 + wrp;           // 4096 blocks * 8 warps = 32768
    const float* xr = x + (size_t)tok * D_;
    float s = 0.f;
    #pragma unroll 8
    for (int i = lane; i < D_; i += 32) s += xr[i] * ws[i];
    #pragma unroll
    for (int o = 16; o > 0; o >>= 1) s += __shfl_xor_sync(0xffffffffu, s, o);
    if (lane == 0) {
        out_scores[tok] = s + bsm[0];
        inv[tok] = -1;
    }
}

// ---------------- top-256 per 2048-token full segment, indices sorted asc ----
__global__ void topk_kernel(const float* __restrict__ scores,
                            int* __restrict__ sel, int* __restrict__ inv) {
    __shared__ float sc[FULL_];
    __shared__ int   si[FULL_];
    int tid = threadIdx.x;                    // 1024 threads
    int f = blockIdx.x & (NFULL_ - 1);
    int b = blockIdx.x >> 2;
    int base = b * S_ + f * FULL_;
    for (int e = tid; e < FULL_; e += 1024) { sc[e] = scores[base + e]; si[e] = e; }
    __syncthreads();
    // bitonic sort DESCENDING by score
    for (int k = 2; k <= FULL_; k <<= 1) {
        for (int j = k >> 1; j > 0; j >>= 1) {
            for (int i = tid; i < FULL_; i += 1024) {
                int ixj = i ^ j;
                if (ixj > i) {
                    bool up = ((i & k) == 0);
                    float a = sc[i], c = sc[ixj];
                    bool sw = up ? (a < c) : (a > c);
                    if (sw) {
                        sc[i] = c; sc[ixj] = a;
                        int t = si[i]; si[i] = si[ixj]; si[ixj] = t;
                    }
                }
            }
            __syncthreads();
        }
    }
    // sort the winning 256 indices ASCENDING
    for (int k = 2; k <= SEG_; k <<= 1) {
        for (int j = k >> 1; j > 0; j >>= 1) {
            if (tid < SEG_) {
                int i = tid, ixj = i ^ j;
                if (ixj > i) {
                    bool up = ((i & k) == 0);
                    int a = si[i], c = si[ixj];
                    bool sw = up ? (a > c) : (a < c);
                    if (sw) { si[i] = c; si[ixj] = a; }
                }
            }
            __syncthreads();
        }
    }
    if (tid < SEG_) {
        int idx = si[tid];
        int gt = b * T_ + f * SEG_ + tid;     // position in selected sequence
        sel[gt] = f * FULL_ + idx;            // within-batch token index
        inv[base + idx] = gt;
    }
}

// ---------------- gather selected rows ---------------------------------------
__global__ void gather_kernel(const float* __restrict__ x,
                              const int* __restrict__ sel,
                              float* __restrict__ xsel) {
    int t = blockIdx.x;                       // 0..TT_-1
    int b = t >> 10;
    int src = sel[t];
    const float4* xr = (const float4*)(x + ((size_t)b * S_ + src) * D_);
    float4* o = (float4*)(xsel + (size_t)t * D_);
    o[threadIdx.x] = xr[threadIdx.x];         // 256 threads * float4 = 1024
}

// ---------------- generic SGEMM: C(MxN) = A(MxK) @ W(KxN) (+bias)(+relu) -----
// 128x128 tile, BK=8, 256 threads, 8x8 micro-tile, global->reg double buffer.
template <bool RELU, bool BIAS>
__global__ void __launch_bounds__(256)
sgemm_kernel(const float* __restrict__ A, const float* __restrict__ W,
             const float* __restrict__ bias, float* __restrict__ C,
             int M, int N, int K) {
    __shared__ float As[8][128];
    __shared__ float Ws[8][128];
    int tid = threadIdx.x;
    int tx = tid & 15, ty = tid >> 4;
    int bm = blockIdx.y * 128, bn = blockIdx.x * 128;

    int am = tid >> 1;
    int ak = (tid & 1) * 4;
    int wk = tid >> 5;
    int wn = (tid & 31) * 4;
    const float* Aptr = A + (size_t)(bm + am) * K + ak;
    const float* Wptr = W + (size_t)wk * N + bn + wn;

    float acc[8][8] = {};

    // prefetch first K-slice into registers
    float4 avr = *(const float4*)(Aptr);
    float4 wvr = *(const float4*)(Wptr);

    for (int k0 = 0; k0 < K; k0 += 8) {
        // commit current slice to smem
        As[ak + 0][am] = avr.x; As[ak + 1][am] = avr.y;
        As[ak + 2][am] = avr.z; As[ak + 3][am] = avr.w;
        *(float4*)&Ws[wk][wn] = wvr;
        __syncthreads();

        // prefetch next slice (hidden behind the FMA block)
        if (k0 + 8 < K) {
            avr = *(const float4*)(Aptr + k0 + 8);
            wvr = *(const float4*)(Wptr + (size_t)(k0 + 8) * N);
        }

        #pragma unroll
        for (int kk = 0; kk < 8; kk++) {
            float a[8], w[8];
            *(float4*)(a)     = *(float4*)&As[kk][ty * 8];
            *(float4*)(a + 4) = *(float4*)&As[kk][ty * 8 + 4];
            *(float4*)(w)     = *(float4*)&Ws[kk][tx * 8];
            *(float4*)(w + 4) = *(float4*)&Ws[kk][tx * 8 + 4];
            #pragma unroll
            for (int i = 0; i < 8; i++)
                #pragma unroll
                for (int j = 0; j < 8; j++)
                    acc[i][j] += a[i] * w[j];
        }
        __syncthreads();
    }
    float bv[8];
    #pragma unroll
    for (int j = 0; j < 8; j++) bv[j] = BIAS ? bias[bn + tx * 8 + j] : 0.f;
    #pragma unroll
    for (int i = 0; i < 8; i++) {
        int row = bm + ty * 8 + i;
        float o[8];
        #pragma unroll
        for (int j = 0; j < 8; j++) {
            float v = acc[i][j] + bv[j];
            o[j] = RELU ? fmaxf(v, 0.f) : v;
        }
        float* cp = C + (size_t)row * N + bn + tx * 8;
        *(float4*)(cp)     = *(float4*)(o);
        *(float4*)(cp + 4) = *(float4*)(o + 4);
    }
}

// ---------------- memory / z init -------------------------------------------
__global__ void init_mem_kernel(float* __restrict__ mem, float* __restrict__ z) {
    int i = blockIdx.x * 256 + threadIdx.x;
    if (i < B_ * H_ * DK_ * DV_) mem[i] = 0.f;
    if (i < B_ * H_ * DK_) z[i] = 1.0f / (float)DK_;
}

// ---------------- attention for one segment ----------------------------------
// grid 128 = B*H*4 q-tiles; 256 threads. Uses mem/z state BEFORE update.
#define QS_STR 68
#define LG_STR 260
#define ATTN_SMEM ((64 * QS_STR * 2 + 64 * LG_STR + 64) * 4)

__global__ void __launch_bounds__(256)
attn_seg_kernel(const float* __restrict__ gq, const float* __restrict__ gk,
                const float* __restrict__ gv, const float* __restrict__ mem,
                const float* __restrict__ zg, const float* __restrict__ betas,
                float* __restrict__ gatt, int seg) {
    extern __shared__ float sm[];
    float* qs = sm;                    // 64 x 68
    float* ks = qs + 64 * QS_STR;      // 64 x 68 (stage for K / V / mem)
    float* lg = ks + 64 * QS_STR;      // 64 x 260 (logits/P, then sq)
    float* den = lg + 64 * LG_STR;     // 64

    int tid = threadIdx.x;
    int qt = blockIdx.x & 3;
    int h  = (blockIdx.x >> 2) & 7;
    int b  = blockIdx.x >> 5;
    int segbase = b * T_ + seg * SEG_;
    int qbase = segbase + qt * 64;
    int tx = tid & 15, ty = tid >> 4;
    int ty4 = ty * 4, tx4 = tx * 4;
    int bh = b * H_ + h;

    // load q tile
    for (int e = tid; e < 4096; e += 256) {
        int i = e >> 6, d = e & 63;
        qs[i * QS_STR + d] = gq[(size_t)(qbase + i) * HD_ + h * DK_ + d];
    }

    // ---- logits = q k^T / sqrt(DK) ----
    for (int kc = 0; kc < 4; kc++) {
        __syncthreads();
        for (int e = tid; e < 4096; e += 256) {
            int i = e >> 6, d = e & 63;
            ks[i * QS_STR + d] = gk[(size_t)(segbase + kc * 64 + i) * HD_ + h * DK_ + d];
        }
        __syncthreads();
        float acc[4][4] = {};
        #pragma unroll 4
        for (int k = 0; k < 64; k++) {
            float a[4], c[4];
            #pragma unroll
            for (int i = 0; i < 4; i++) a[i] = qs[(ty4 + i) * QS_STR + k];
            #pragma unroll
            for (int j = 0; j < 4; j++) c[j] = ks[(tx4 + j) * QS_STR + k];
            #pragma unroll
            for (int i = 0; i < 4; i++)
                #pragma unroll
                for (int j = 0; j < 4; j++) acc[i][j] += a[i] * c[j];
        }
        #pragma unroll
        for (int i = 0; i < 4; i++)
            #pragma unroll
            for (int j = 0; j < 4; j++)
                lg[(ty4 + i) * LG_STR + kc * 64 + tx4 + j] = acc[i][j] * 0.125f;
    }
    __syncthreads();

    // ---- softmax over 256 keys, 8 warps x 8 rows ----
    int lane = tid & 31, wrp = tid >> 5;
    for (int r = wrp; r < 64; r += 8) {
        float* row = lg + r * LG_STR;
        float m = -1e30f;
        #pragma unroll
        for (int t = lane; t < 256; t += 32) m = fmaxf(m, row[t]);
        #pragma unroll
        for (int o = 16; o > 0; o >>= 1) m = fmaxf(m, __shfl_xor_sync(0xffffffffu, m, o));
        float s = 0.f;
        #pragma unroll
        for (int t = lane; t < 256; t += 32) {
            float e = __expf(row[t] - m);
            row[t] = e; s += e;
        }
        #pragma unroll
        for (int o = 16; o > 0; o >>= 1) s += __shfl_xor_sync(0xffffffffu, s, o);
        float invs = 1.f / s;
        #pragma unroll
        for (int t = lane; t < 256; t += 32) row[t] *= invs;
    }
    __syncthreads();

    // ---- att_dot = P @ V ----
    float c2[4][4] = {};
    for (int vc = 0; vc < 4; vc++) {
        __syncthreads();
        for (int e = tid; e < 4096; e += 256) {
            int i = e >> 6, d = e & 63;
            ks[i * QS_STR + d] = gv[(size_t)(segbase + vc * 64 + i) * HD_ + h * DK_ + d];
        }
        __syncthreads();
        #pragma unroll 4
        for (int t = 0; t < 64; t++) {
            float p[4], v[4];
            #pragma unroll
            for (int i = 0; i < 4; i++) p[i] = lg[(ty4 + i) * LG_STR + vc * 64 + t];
            #pragma unroll
            for (int j = 0; j < 4; j++) v[j] = ks[t * QS_STR + tx4 + j];
            #pragma unroll
            for (int i = 0; i < 4; i++)
                #pragma unroll
                for (int j = 0; j < 4; j++) c2[i][j] += p[i] * v[j];
        }
    }
    __syncthreads();

    // ---- att_mem = sq @ mem / (sq @ z) ----  (sq tile reuses lg, mem -> ks)
    for (int e = tid; e < 4096; e += 256) {
        int i = e >> 6, d = e & 63;
        lg[i * QS_STR + d] = elup1(qs[i * QS_STR + d]);
        ks[i * QS_STR + d] = mem[((size_t)bh * DK_ + i) * DV_ + d];
    }
    __syncthreads();
    if (tid < 64) {
        float s = 0.f;
        #pragma unroll 8
        for (int k = 0; k < 64; k++) s += lg[tid * QS_STR + k] * zg[bh * DK_ + k];
        den[tid] = s;
    }
    float c3[4][4] = {};
    #pragma unroll 4
    for (int k = 0; k < 64; k++) {
        float a[4], m4[4];
        #pragma unroll
        for (int i = 0; i < 4; i++) a[i] = lg[(ty4 + i) * QS_STR + k];
        #pragma unroll
        for (int j = 0; j < 4; j++) m4[j] = ks[k * QS_STR + tx4 + j];
        #pragma unroll
        for (int i = 0; i < 4; i++)
            #pragma unroll
            for (int j = 0; j < 4; j++) c3[i][j] += a[i] * m4[j];
    }
    __syncthreads();

    // ---- gate blend + store ----
    #pragma unroll
    for (int j = 0; j < 4; j++) {
        float bvj = betas[h * DV_ + tx4 + j];
        float gate = 1.f / (1.f + __expf(-bvj));
        #pragma unroll
        for (int i = 0; i < 4; i++) {
            int row = ty4 + i;
            float att = gate * (c3[i][j] / den[row]) + (1.f - gate) * c2[i][j];
            gatt[(size_t)(qbase + row) * HD_ + h * DV_ + tx4 + j] = att;
        }
    }
}

// ---------------- mem/z linear update for one segment -------------------------
__global__ void __launch_bounds__(256)
mem_update_kernel(const float* __restrict__ gk, const float* __restrict__ gv,
                  float* __restrict__ mem, float* __restrict__ zg, int seg) {
    __shared__ float ks[64 * QS_STR];
    __shared__ float vs[64 * QS_STR];
    int tid = threadIdx.x;
    int h = blockIdx.x & 7, b = blockIdx.x >> 3;
    int segbase = b * T_ + seg * SEG_;
    int tx = tid & 15, ty = tid >> 4;
    int ty4 = ty * 4, tx4 = tx * 4;
    int bh = b * H_ + h;

    float c[4][4] = {};
    float zacc = 0.f;
    for (int tc = 0; tc < 4; tc++) {
        __syncthreads();
        for (int e = tid; e < 4096; e += 256) {
            int i = e >> 6, d = e & 63;
            size_t gi = (size_t)(segbase + tc * 64 + i) * HD_ + h * DK_ + d;
            ks[i * QS_STR + d] = elup1(gk[gi]);   // sk
            vs[i * QS_STR + d] = gv[gi];
        }
        __syncthreads();
        #pragma unroll 4
        for (int t = 0; t < 64; t++) {
            float sk[4], v[4];
            #pragma unroll
            for (int i = 0; i < 4; i++) sk[i] = ks[t * QS_STR + ty4 + i];
            #pragma unroll
            for (int j = 0; j < 4; j++) v[j] = vs[t * QS_STR + tx4 + j];
            #pragma unroll
            for (int i = 0; i < 4; i++)
                #pragma unroll
                for (int j = 0; j < 4; j++) c[i][j] += sk[i] * v[j];
        }
        if (tid < 64) {
            #pragma unroll 8
            for (int t = 0; t < 64; t++) zacc += ks[t * QS_STR + tid];
        }
    }
    #pragma unroll
    for (int i = 0; i < 4; i++)
        #pragma unroll
        for (int j = 0; j < 4; j++)
            mem[((size_t)bh * DK_ + ty4 + i) * DV_ + tx4 + j] += c[i][j];
    if (tid < 64) zg[bh * DK_ + tid] += zacc;
}

// ---------------- scatter-add residual + LayerNorm + mask ---------------------
__global__ void ln_kernel(const float* __restrict__ x, const float* __restrict__ hh,
                          const int* __restrict__ inv,
                          const float* __restrict__ gamma, const float* __restrict__ beta,
                          float* __restrict__ y, float* __restrict__ mask) {
    __shared__ float rs[8], rs2[8], bc[2];
    int tok = blockIdx.x, tid = threadIdx.x;
    float4 v = ((const float4*)(x + (size_t)tok * D_))[tid];
    int iv = inv[tok];
    if (iv >= 0) {
        float4 hv = ((const float4*)(hh + (size_t)iv * D_))[tid];
        v.x += hv.x; v.y += hv.y; v.z += hv.z; v.w += hv.w;
    }
    float s = v.x + v.y + v.z + v.w;
    float s2 = v.x * v.x + v.y * v.y + v.z * v.z + v.w * v.w;
    #pragma unroll
    for (int o = 16; o > 0; o >>= 1) {
        s += __shfl_xor_sync(0xffffffffu, s, o);
        s2 += __shfl_xor_sync(0xffffffffu, s2, o);
    }
    int lane = tid & 31, w = tid >> 5;
    if (lane == 0) { rs[w] = s; rs2[w] = s2; }
    __syncthreads();
    if (tid == 0) {
        float S = 0.f, S2 = 0.f;
        #pragma unroll
        for (int i = 0; i < 8; i++) { S += rs[i]; S2 += rs2[i]; }
        bc[0] = S; bc[1] = S2;
    }
    __syncthreads();
    float mu = bc[0] * (1.f / D_);
    float var = bc[1] * (1.f / D_) - mu * mu;
    float istd = rsqrtf(var + 1e-5f);
    float4 g = ((const float4*)gamma)[tid];
    float4 bb = ((const float4*)beta)[tid];
    float4 o;
    o.x = (v.x - mu) * istd * g.x + bb.x;
    o.y = (v.y - mu) * istd * g.y + bb.y;
    o.z = (v.z - mu) * istd * g.z + bb.z;
    o.w = (v.w - mu) * istd * g.w + bb.w;
    ((float4*)(y + (size_t)tok * D_))[tid] = o;
    if (tid == 0) mask[tok] = (iv >= 0) ? 1.f : 0.f;
}

// ---------------- launch ------------------------------------------------------
extern "C" void kernel_launch(void* const* d_in, const int* in_sizes, int n_in,
                              void* d_out, int out_size) {
    const float* x        = (const float*)d_in[0];
    const float* w_sample = (const float*)d_in[1];
    const float* b_sample = (const float*)d_in[2];
    const float* wq       = (const float*)d_in[3];
    const float* wk       = (const float*)d_in[4];
    const float* wv       = (const float*)d_in[5];
    const float* w_out    = (const float*)d_in[6];
    const float* betas    = (const float*)d_in[7];
    const float* w1       = (const float*)d_in[8];
    const float* b1       = (const float*)d_in[9];
    const float* w2       = (const float*)d_in[10];
    const float* b2       = (const float*)d_in[11];
    const float* ln_gamma = (const float*)d_in[12];
    const float* ln_beta  = (const float*)d_in[13];

    float* out = (float*)d_out;
    float* y_out    = out;
    float* mask_out = out + (size_t)B_ * S_ * D_;
    float* sc_out   = mask_out + (size_t)B_ * S_;

    float *xsel, *q, *k, *v, *att, *a, *h1, *h, *mem, *z;
    int *sel, *inv;
    cudaGetSymbolAddress((void**)&xsel, g_xsel);
    cudaGetSymbolAddress((void**)&q,    g_q);
    cudaGetSymbolAddress((void**)&k,    g_k);
    cudaGetSymbolAddress((void**)&v,    g_v);
    cudaGetSymbolAddress((void**)&att,  g_att);
    cudaGetSymbolAddress((void**)&a,    g_a);
    cudaGetSymbolAddress((void**)&h1,   g_h1);
    cudaGetSymbolAddress((void**)&h,    g_h);
    cudaGetSymbolAddress((void**)&mem,  g_mem);
    cudaGetSymbolAddress((void**)&z,    g_z);
    cudaGetSymbolAddress((void**)&sel,  g_sel);
    cudaGetSymbolAddress((void**)&inv,  g_inv);

    cudaFuncSetAttribute(attn_seg_kernel,
                         cudaFuncAttributeMaxDynamicSharedMemorySize, ATTN_SMEM);

    scores_kernel<<<B_ * S_ / 8, 256>>>(x, w_sample, b_sample, sc_out, inv);
    topk_kernel<<<B_ * NFULL_, 1024>>>(sc_out, sel, inv);
    gather_kernel<<<TT_, 256>>>(x, sel, xsel);

    dim3 blk(256);
    sgemm_kernel<false, false><<<dim3(HD_ / 128, TT_ / 128), blk>>>(xsel, wq, nullptr, q, TT_, HD_, D_);
    sgemm_kernel<false, false><<<dim3(HD_ / 128, TT_ / 128), blk>>>(xsel, wk, nullptr, k, TT_, HD_, D_);
    sgemm_kernel<false, false><<<dim3(HD_ / 128, TT_ / 128), blk>>>(xsel, wv, nullptr, v, TT_, HD_, D_);

    init_mem_kernel<<<(B_ * H_ * DK_ * DV_ + 255) / 256, 256>>>(mem, z);
    for (int s = 0; s < 4; s++) {
        attn_seg_kernel<<<B_ * H_ * 4, 256, ATTN_SMEM>>>(q, k, v, mem, z, betas, att, s);
        mem_update_kernel<<<B_ * H_, 256>>>(k, v, mem, z, s);
    }

    sgemm_kernel<false, false><<<dim3(D_ / 128, TT_ / 128), blk>>>(att, w_out, nullptr, a, TT_, D_, HD_);
    sgemm_kernel<true,  true ><<<dim3(DH_ / 128, TT_ / 128), blk>>>(a, w1, b1, h1, TT_, DH_, D_);
    sgemm_kernel<false, true ><<<dim3(D_ / 128, TT_ / 128), blk>>>(h1, w2, b2, h, TT_, D_, DH_);

    ln_kernel<<<B_ * S_, 256>>>(x, h, inv, ln_gamma, ln_beta, y_out, mask_out);
}

// round 3
// speedup vs baseline: 2.2406x; 2.2406x over previous
#include <cuda_runtime.h>
#include <math.h>

#define B_ 4
#define S_ 8192
#define D_ 1024
#define H_ 8
#define DK_ 64
#define DV_ 64
#define DH_ 4096
#define FULL_ 2048
#define SEG_ 256
#define NFULL_ 4
#define T_ 1024           // selected tokens per batch
#define TT_ 4096          // total selected tokens
#define HD_ 512           // H*DK = H*DV

// ---------------- scratch (static device globals; no allocation) -------------
__device__ float g_xsel[TT_ * D_];
__device__ float g_q[TT_ * HD_];
__device__ float g_k[TT_ * HD_];
__device__ float g_v[TT_ * HD_];
__device__ float g_att[TT_ * HD_];
__device__ float g_a[TT_ * D_];
__device__ float g_h1[(size_t)TT_ * DH_];
__device__ float g_h[TT_ * D_];
__device__ float g_mseg[B_ * H_ * 4 * DK_ * DV_];   // per-segment sk^T v
__device__ float g_zseg[B_ * H_ * 4 * DK_];
__device__ float g_mstate[B_ * H_ * 4 * DK_ * DV_]; // prefix state before seg s
__device__ float g_zstate[B_ * H_ * 4 * DK_];
__device__ int   g_sel[TT_];
__device__ int   g_inv[B_ * S_];

__device__ __forceinline__ float elup1(float x) {
    return x > 0.f ? x + 1.f : __expf(x);
}

__device__ __forceinline__ float tf32r(float x) {
    unsigned r;
    asm("cvt.rna.tf32.f32 %0, %1;" : "=r"(r) : "f"(x));
    return __uint_as_float(r);
}

// ---------------- scores: s = x @ w_sample + b ; also init g_inv = -1 --------
__global__ void scores_kernel(const float* __restrict__ x,
                              const float* __restrict__ w,
                              const float* __restrict__ bsm,
                              float* __restrict__ out_scores,
                              int* __restrict__ inv) {
    __shared__ float ws[D_];
    int tid = threadIdx.x;
    for (int e = tid; e < D_; e += 256) ws[e] = w[e];
    __syncthreads();
    int lane = tid & 31, wrp = tid >> 5;
    int tok = blockIdx.x * 8 + wrp;
    const float* xr = x + (size_t)tok * D_;
    float s = 0.f;
    #pragma unroll 8
    for (int i = lane; i < D_; i += 32) s += xr[i] * ws[i];
    #pragma unroll
    for (int o = 16; o > 0; o >>= 1) s += __shfl_xor_sync(0xffffffffu, s, o);
    if (lane == 0) {
        out_scores[tok] = s + bsm[0];
        inv[tok] = -1;
    }
}

// ---------------- top-256 per 2048-token full segment, indices sorted asc ----
__global__ void topk_kernel(const float* __restrict__ scores,
                            int* __restrict__ sel, int* __restrict__ inv) {
    __shared__ float sc[FULL_];
    __shared__ int   si[FULL_];
    int tid = threadIdx.x;                    // 1024 threads
    int f = blockIdx.x & (NFULL_ - 1);
    int b = blockIdx.x >> 2;
    int base = b * S_ + f * FULL_;
    for (int e = tid; e < FULL_; e += 1024) { sc[e] = scores[base + e]; si[e] = e; }
    __syncthreads();
    for (int k = 2; k <= FULL_; k <<= 1) {
        for (int j = k >> 1; j > 0; j >>= 1) {
            for (int i = tid; i < FULL_; i += 1024) {
                int ixj = i ^ j;
                if (ixj > i) {
                    bool up = ((i & k) == 0);
                    float a = sc[i], c = sc[ixj];
                    bool sw = up ? (a < c) : (a > c);
                    if (sw) {
                        sc[i] = c; sc[ixj] = a;
                        int t = si[i]; si[i] = si[ixj]; si[ixj] = t;
                    }
                }
            }
            __syncthreads();
        }
    }
    for (int k = 2; k <= SEG_; k <<= 1) {
        for (int j = k >> 1; j > 0; j >>= 1) {
            if (tid < SEG_) {
                int i = tid, ixj = i ^ j;
                if (ixj > i) {
                    bool up = ((i & k) == 0);
                    int a = si[i], c = si[ixj];
                    bool sw = up ? (a > c) : (a < c);
                    if (sw) { si[i] = c; si[ixj] = a; }
                }
            }
            __syncthreads();
        }
    }
    if (tid < SEG_) {
        int idx = si[tid];
        int gt = b * T_ + f * SEG_ + tid;
        sel[gt] = f * FULL_ + idx;
        inv[base + idx] = gt;
    }
}

// ---------------- gather selected rows ---------------------------------------
__global__ void gather_kernel(const float* __restrict__ x,
                              const int* __restrict__ sel,
                              float* __restrict__ xsel) {
    int t = blockIdx.x;
    int b = t >> 10;
    int src = sel[t];
    const float4* xr = (const float4*)(x + ((size_t)b * S_ + src) * D_);
    float4* o = (float4*)(xsel + (size_t)t * D_);
    o[threadIdx.x] = xr[threadIdx.x];
}

// ---------------- TF32 tensor-core GEMM: C = A(MxK) @ W(KxN) (+bias)(+relu) --
// 128x128 tile, BK=16, 256 thr, 8 warps (2x4), warp tile 64x32, m16n8k8 mma.
struct P3 {
    const float *W0, *W1, *W2;
    float *C0, *C1, *C2;
};

template <bool RELU, bool BIAS>
__global__ void __launch_bounds__(256, 2)
tf32gemm_kernel(const float* __restrict__ A, P3 p,
                const float* __restrict__ bias, int N, int K) {
    __shared__ float As[128][20];
    __shared__ float Ws[16][136];
    const float* W = blockIdx.z == 0 ? p.W0 : (blockIdx.z == 1 ? p.W1 : p.W2);
    float* C       = blockIdx.z == 0 ? p.C0 : (blockIdx.z == 1 ? p.C1 : p.C2);

    int tid = threadIdx.x;
    int bm = blockIdx.y * 128, bn = blockIdx.x * 128;
    int lane = tid & 31, wid = tid >> 5;
    int gid = lane >> 2, tig = lane & 3;
    int wm = (wid & 1) * 64, wn = (wid >> 1) * 32;

    int aRow = tid >> 1, aCol = (tid & 1) * 8;
    int wRow = tid >> 4, wCol = (tid & 15) * 8;
    const float* Aptr = A + (size_t)(bm + aRow) * K + aCol;
    const float* Wptr = W + (size_t)wRow * N + bn + wCol;

    float acc[4][4][4];
    #pragma unroll
    for (int i = 0; i < 4; i++)
        #pragma unroll
        for (int j = 0; j < 4; j++)
            #pragma unroll
            for (int r = 0; r < 4; r++) acc[i][j][r] = 0.f;

    float4 pa0 = *(const float4*)(Aptr);
    float4 pa1 = *(const float4*)(Aptr + 4);
    float4 pw0 = *(const float4*)(Wptr);
    float4 pw1 = *(const float4*)(Wptr + 4);

    for (int k0 = 0; k0 < K; k0 += 16) {
        *(float4*)&As[aRow][aCol] =
            make_float4(tf32r(pa0.x), tf32r(pa0.y), tf32r(pa0.z), tf32r(pa0.w));
        *(float4*)&As[aRow][aCol + 4] =
            make_float4(tf32r(pa1.x), tf32r(pa1.y), tf32r(pa1.z), tf32r(pa1.w));
        *(float4*)&Ws[wRow][wCol] =
            make_float4(tf32r(pw0.x), tf32r(pw0.y), tf32r(pw0.z), tf32r(pw0.w));
        *(float4*)&Ws[wRow][wCol + 4] =
            make_float4(tf32r(pw1.x), tf32r(pw1.y), tf32r(pw1.z), tf32r(pw1.w));
        __syncthreads();
        if (k0 + 16 < K) {
            pa0 = *(const float4*)(Aptr + k0 + 16);
            pa1 = *(const float4*)(Aptr + k0 + 20);
            pw0 = *(const float4*)(Wptr + (size_t)(k0 + 16) * N);
            pw1 = *(const float4*)(Wptr + (size_t)(k0 + 16) * N + 4);
        }
        #pragma unroll
        for (int kk = 0; kk < 16; kk += 8) {
            unsigned a[4][4], b[4][2];
            #pragma unroll
            for (int mt = 0; mt < 4; mt++) {
                int r0 = wm + mt * 16 + gid;
                a[mt][0] = __float_as_uint(As[r0][kk + tig]);
                a[mt][1] = __float_as_uint(As[r0 + 8][kk + tig]);
                a[mt][2] = __float_as_uint(As[r0][kk + tig + 4]);
                a[mt][3] = __float_as_uint(As[r0 + 8][kk + tig + 4]);
            }
            #pragma unroll
            for (int nt = 0; nt < 4; nt++) {
                int cn = wn + nt * 8 + gid;
                b[nt][0] = __float_as_uint(Ws[kk + tig][cn]);
                b[nt][1] = __float_as_uint(Ws[kk + tig + 4][cn]);
            }
            #pragma unroll
            for (int mt = 0; mt < 4; mt++)
                #pragma unroll
                for (int nt = 0; nt < 4; nt++)
                    asm volatile(
                        "mma.sync.aligned.m16n8k8.row.col.f32.tf32.tf32.f32 "
                        "{%0,%1,%2,%3}, {%4,%5,%6,%7}, {%8,%9}, {%0,%1,%2,%3};"
                        : "+f"(acc[mt][nt][0]), "+f"(acc[mt][nt][1]),
                          "+f"(acc[mt][nt][2]), "+f"(acc[mt][nt][3])
                        : "r"(a[mt][0]), "r"(a[mt][1]), "r"(a[mt][2]), "r"(a[mt][3]),
                          "r"(b[nt][0]), "r"(b[nt][1]));
        }
        __syncthreads();
    }

    #pragma unroll
    for (int nt = 0; nt < 4; nt++) {
        int cn = bn + wn + nt * 8 + tig * 2;
        float b0 = BIAS ? bias[cn] : 0.f;
        float b1 = BIAS ? bias[cn + 1] : 0.f;
        #pragma unroll
        for (int mt = 0; mt < 4; mt++) {
            int r = bm + wm + mt * 16 + gid;
            float v0 = acc[mt][nt][0] + b0;
            float v1 = acc[mt][nt][1] + b1;
            float v2 = acc[mt][nt][2] + b0;
            float v3 = acc[mt][nt][3] + b1;
            if (RELU) {
                v0 = fmaxf(v0, 0.f); v1 = fmaxf(v1, 0.f);
                v2 = fmaxf(v2, 0.f); v3 = fmaxf(v3, 0.f);
            }
            *(float2*)&C[(size_t)r * N + cn] = make_float2(v0, v1);
            *(float2*)&C[(size_t)(r + 8) * N + cn] = make_float2(v2, v3);
        }
    }
}

// ---------------- per-segment memory contribution M_s = sk^T v, z_s ----------
#define QS_STR 68
__global__ void __launch_bounds__(256)
seg_mem_kernel(const float* __restrict__ gk, const float* __restrict__ gv,
               float* __restrict__ mseg, float* __restrict__ zseg) {
    __shared__ float ks[64 * QS_STR];
    __shared__ float vs[64 * QS_STR];
    int tid = threadIdx.x;
    int s = blockIdx.x & 3;
    int h = (blockIdx.x >> 2) & 7;
    int b = blockIdx.x >> 5;
    int segbase = b * T_ + s * SEG_;
    int tx = tid & 15, ty = tid >> 4;
    int ty4 = ty * 4, tx4 = tx * 4;
    int bhs = (b * H_ + h) * 4 + s;

    float c[4][4] = {};
    float zacc = 0.f;
    for (int tc = 0; tc < 4; tc++) {
        __syncthreads();
        for (int e = tid; e < 4096; e += 256) {
            int i = e >> 6, d = e & 63;
            size_t gi = (size_t)(segbase + tc * 64 + i) * HD_ + h * DK_ + d;
            ks[i * QS_STR + d] = elup1(gk[gi]);   // sk
            vs[i * QS_STR + d] = gv[gi];
        }
        __syncthreads();
        #pragma unroll 4
        for (int t = 0; t < 64; t++) {
            float sk[4], v[4];
            #pragma unroll
            for (int i = 0; i < 4; i++) sk[i] = ks[t * QS_STR + ty4 + i];
            #pragma unroll
            for (int j = 0; j < 4; j++) v[j] = vs[t * QS_STR + tx4 + j];
            #pragma unroll
            for (int i = 0; i < 4; i++)
                #pragma unroll
                for (int j = 0; j < 4; j++) c[i][j] += sk[i] * v[j];
        }
        if (tid < 64) {
            #pragma unroll 8
            for (int t = 0; t < 64; t++) zacc += ks[t * QS_STR + tid];
        }
    }
    #pragma unroll
    for (int i = 0; i < 4; i++)
        #pragma unroll
        for (int j = 0; j < 4; j++)
            mseg[((size_t)bhs * DK_ + ty4 + i) * DV_ + tx4 + j] = c[i][j];
    if (tid < 64) zseg[bhs * DK_ + tid] = zacc;
}

// ---------------- prefix states: state_s = mem0 + sum_{s'<s} M_s' ------------
__global__ void prefix_kernel(const float* __restrict__ mseg,
                              const float* __restrict__ zseg,
                              float* __restrict__ mstate,
                              float* __restrict__ zstate) {
    int bh = blockIdx.x;                      // 0..31
    int tid = threadIdx.x;                    // 256
    size_t base = (size_t)bh * 4 * 4096;
    for (int e = tid; e < 4096; e += 256) {
        float acc = 0.f;
        #pragma unroll
        for (int s = 0; s < 4; s++) {
            mstate[base + (size_t)s * 4096 + e] = acc;
            acc += mseg[base + (size_t)s * 4096 + e];
        }
    }
    if (tid < 64) {
        size_t zb = (size_t)bh * 4 * 64;
        float acc = 1.0f / (float)DK_;
        #pragma unroll
        for (int s = 0; s < 4; s++) {
            zstate[zb + s * 64 + tid] = acc;
            acc += zseg[zb + s * 64 + tid];
        }
    }
}

// ---------------- attention for all segments in parallel ---------------------
#define LG_STR 260
#define ATTN_SMEM ((64 * QS_STR * 2 + 64 * LG_STR + 64) * 4)

__global__ void __launch_bounds__(256)
attn_full_kernel(const float* __restrict__ gq, const float* __restrict__ gk,
                 const float* __restrict__ gv, const float* __restrict__ mstate,
                 const float* __restrict__ zstate, const float* __restrict__ betas,
                 float* __restrict__ gatt) {
    extern __shared__ float sm[];
    float* qs = sm;                    // 64 x 68
    float* ks = qs + 64 * QS_STR;      // 64 x 68 (stage for K / V / mem)
    float* lg = ks + 64 * QS_STR;      // 64 x 260 (logits/P, then sq)
    float* den = lg + 64 * LG_STR;     // 64

    int tid = threadIdx.x;
    int qt = blockIdx.x & 3;
    int s  = (blockIdx.x >> 2) & 3;
    int h  = (blockIdx.x >> 4) & 7;
    int b  = blockIdx.x >> 7;
    int segbase = b * T_ + s * SEG_;
    int qbase = segbase + qt * 64;
    int tx = tid & 15, ty = tid >> 4;
    int ty4 = ty * 4, tx4 = tx * 4;
    int bhs = (b * H_ + h) * 4 + s;

    for (int e = tid; e < 4096; e += 256) {
        int i = e >> 6, d = e & 63;
        qs[i * QS_STR + d] = gq[(size_t)(qbase + i) * HD_ + h * DK_ + d];
    }

    // ---- logits = q k^T / sqrt(DK) ----
    for (int kc = 0; kc < 4; kc++) {
        __syncthreads();
        for (int e = tid; e < 4096; e += 256) {
            int i = e >> 6, d = e & 63;
            ks[i * QS_STR + d] = gk[(size_t)(segbase + kc * 64 + i) * HD_ + h * DK_ + d];
        }
        __syncthreads();
        float acc[4][4] = {};
        #pragma unroll 4
        for (int k = 0; k < 64; k++) {
            float a[4], c[4];
            #pragma unroll
            for (int i = 0; i < 4; i++) a[i] = qs[(ty4 + i) * QS_STR + k];
            #pragma unroll
            for (int j = 0; j < 4; j++) c[j] = ks[(tx4 + j) * QS_STR + k];
            #pragma unroll
            for (int i = 0; i < 4; i++)
                #pragma unroll
                for (int j = 0; j < 4; j++) acc[i][j] += a[i] * c[j];
        }
        #pragma unroll
        for (int i = 0; i < 4; i++)
            #pragma unroll
            for (int j = 0; j < 4; j++)
                lg[(ty4 + i) * LG_STR + kc * 64 + tx4 + j] = acc[i][j] * 0.125f;
    }
    __syncthreads();

    // ---- softmax over 256 keys ----
    int lane = tid & 31, wrp = tid >> 5;
    for (int r = wrp; r < 64; r += 8) {
        float* row = lg + r * LG_STR;
        float m = -1e30f;
        #pragma unroll
        for (int t = lane; t < 256; t += 32) m = fmaxf(m, row[t]);
        #pragma unroll
        for (int o = 16; o > 0; o >>= 1) m = fmaxf(m, __shfl_xor_sync(0xffffffffu, m, o));
        float sum = 0.f;
        #pragma unroll
        for (int t = lane; t < 256; t += 32) {
            float e = __expf(row[t] - m);
            row[t] = e; sum += e;
        }
        #pragma unroll
        for (int o = 16; o > 0; o >>= 1) sum += __shfl_xor_sync(0xffffffffu, sum, o);
        float invs = 1.f / sum;
        #pragma unroll
        for (int t = lane; t < 256; t += 32) row[t] *= invs;
    }
    __syncthreads();

    // ---- att_dot = P @ V ----
    float c2[4][4] = {};
    for (int vc = 0; vc < 4; vc++) {
        __syncthreads();
        for (int e = tid; e < 4096; e += 256) {
            int i = e >> 6, d = e & 63;
            ks[i * QS_STR + d] = gv[(size_t)(segbase + vc * 64 + i) * HD_ + h * DK_ + d];
        }
        __syncthreads();
        #pragma unroll 4
        for (int t = 0; t < 64; t++) {
            float p[4], v[4];
            #pragma unroll
            for (int i = 0; i < 4; i++) p[i] = lg[(ty4 + i) * LG_STR + vc * 64 + t];
            #pragma unroll
            for (int j = 0; j < 4; j++) v[j] = ks[t * QS_STR + tx4 + j];
            #pragma unroll
            for (int i = 0; i < 4; i++)
                #pragma unroll
                for (int j = 0; j < 4; j++) c2[i][j] += p[i] * v[j];
        }
    }
    __syncthreads();

    // ---- att_mem = sq @ mem_state / (sq @ z_state) ----
    for (int e = tid; e < 4096; e += 256) {
        int i = e >> 6, d = e & 63;
        lg[i * QS_STR + d] = elup1(qs[i * QS_STR + d]);
        ks[i * QS_STR + d] = mstate[(size_t)bhs * 4096 + i * 64 + d];
    }
    __syncthreads();
    if (tid < 64) {
        float sd = 0.f;
        #pragma unroll 8
        for (int k = 0; k < 64; k++) sd += lg[tid * QS_STR + k] * zstate[bhs * 64 + k];
        den[tid] = sd;
    }
    float c3[4][4] = {};
    #pragma unroll 4
    for (int k = 0; k < 64; k++) {
        float a[4], m4[4];
        #pragma unroll
        for (int i = 0; i < 4; i++) a[i] = lg[(ty4 + i) * QS_STR + k];
        #pragma unroll
        for (int j = 0; j < 4; j++) m4[j] = ks[k * QS_STR + tx4 + j];
        #pragma unroll
        for (int i = 0; i < 4; i++)
            #pragma unroll
            for (int j = 0; j < 4; j++) c3[i][j] += a[i] * m4[j];
    }
    __syncthreads();

    #pragma unroll
    for (int j = 0; j < 4; j++) {
        float bvj = betas[h * DV_ + tx4 + j];
        float gate = 1.f / (1.f + __expf(-bvj));
        #pragma unroll
        for (int i = 0; i < 4; i++) {
            int row = ty4 + i;
            float att = gate * (c3[i][j] / den[row]) + (1.f - gate) * c2[i][j];
            gatt[(size_t)(qbase + row) * HD_ + h * DV_ + tx4 + j] = att;
        }
    }
}

// ---------------- scatter-add residual + LayerNorm + mask ---------------------
__global__ void ln_kernel(const float* __restrict__ x, const float* __restrict__ hh,
                          const int* __restrict__ inv,
                          const float* __restrict__ gamma, const float* __restrict__ beta,
                          float* __restrict__ y, float* __restrict__ mask) {
    __shared__ float rs[8], rs2[8], bc[2];
    int tok = blockIdx.x, tid = threadIdx.x;
    float4 v = ((const float4*)(x + (size_t)tok * D_))[tid];
    int iv = inv[tok];
    if (iv >= 0) {
        float4 hv = ((const float4*)(hh + (size_t)iv * D_))[tid];
        v.x += hv.x; v.y += hv.y; v.z += hv.z; v.w += hv.w;
    }
    float s = v.x + v.y + v.z + v.w;
    float s2 = v.x * v.x + v.y * v.y + v.z * v.z + v.w * v.w;
    #pragma unroll
    for (int o = 16; o > 0; o >>= 1) {
        s += __shfl_xor_sync(0xffffffffu, s, o);
        s2 += __shfl_xor_sync(0xffffffffu, s2, o);
    }
    int lane = tid & 31, w = tid >> 5;
    if (lane == 0) { rs[w] = s; rs2[w] = s2; }
    __syncthreads();
    if (tid == 0) {
        float S = 0.f, S2 = 0.f;
        #pragma unroll
        for (int i = 0; i < 8; i++) { S += rs[i]; S2 += rs2[i]; }
        bc[0] = S; bc[1] = S2;
    }
    __syncthreads();
    float mu = bc[0] * (1.f / D_);
    float var = bc[1] * (1.f / D_) - mu * mu;
    float istd = rsqrtf(var + 1e-5f);
    float4 g = ((const float4*)gamma)[tid];
    float4 bb = ((const float4*)beta)[tid];
    float4 o;
    o.x = (v.x - mu) * istd * g.x + bb.x;
    o.y = (v.y - mu) * istd * g.y + bb.y;
    o.z = (v.z - mu) * istd * g.z + bb.z;
    o.w = (v.w - mu) * istd * g.w + bb.w;
    ((float4*)(y + (size_t)tok * D_))[tid] = o;
    if (tid == 0) mask[tok] = (iv >= 0) ? 1.f : 0.f;
}

// ---------------- launch ------------------------------------------------------
extern "C" void kernel_launch(void* const* d_in, const int* in_sizes, int n_in,
                              void* d_out, int out_size) {
    const float* x        = (const float*)d_in[0];
    const float* w_sample = (const float*)d_in[1];
    const float* b_sample = (const float*)d_in[2];
    const float* wq       = (const float*)d_in[3];
    const float* wk       = (const float*)d_in[4];
    const float* wv       = (const float*)d_in[5];
    const float* w_out    = (const float*)d_in[6];
    const float* betas    = (const float*)d_in[7];
    const float* w1       = (const float*)d_in[8];
    const float* b1       = (const float*)d_in[9];
    const float* w2       = (const float*)d_in[10];
    const float* b2       = (const float*)d_in[11];
    const float* ln_gamma = (const float*)d_in[12];
    const float* ln_beta  = (const float*)d_in[13];

    float* out = (float*)d_out;
    float* y_out    = out;
    float* mask_out = out + (size_t)B_ * S_ * D_;
    float* sc_out   = mask_out + (size_t)B_ * S_;

    float *xsel, *q, *k, *v, *att, *a, *h1, *h, *mseg, *zseg, *mstate, *zstate;
    int *sel, *inv;
    cudaGetSymbolAddress((void**)&xsel,   g_xsel);
    cudaGetSymbolAddress((void**)&q,      g_q);
    cudaGetSymbolAddress((void**)&k,      g_k);
    cudaGetSymbolAddress((void**)&v,      g_v);
    cudaGetSymbolAddress((void**)&att,    g_att);
    cudaGetSymbolAddress((void**)&a,      g_a);
    cudaGetSymbolAddress((void**)&h1,     g_h1);
    cudaGetSymbolAddress((void**)&h,      g_h);
    cudaGetSymbolAddress((void**)&mseg,   g_mseg);
    cudaGetSymbolAddress((void**)&zseg,   g_zseg);
    cudaGetSymbolAddress((void**)&mstate, g_mstate);
    cudaGetSymbolAddress((void**)&zstate, g_zstate);
    cudaGetSymbolAddress((void**)&sel,    g_sel);
    cudaGetSymbolAddress((void**)&inv,    g_inv);

    cudaFuncSetAttribute(attn_full_kernel,
                         cudaFuncAttributeMaxDynamicSharedMemorySize, ATTN_SMEM);

    scores_kernel<<<B_ * S_ / 8, 256>>>(x, w_sample, b_sample, sc_out, inv);
    topk_kernel<<<B_ * NFULL_, 1024>>>(sc_out, sel, inv);
    gather_kernel<<<TT_, 256>>>(x, sel, xsel);

    dim3 blk(256);
    // fused QKV: grid.z selects the projection
    P3 pqkv = {wq, wk, wv, q, k, v};
    tf32gemm_kernel<false, false><<<dim3(HD_ / 128, TT_ / 128, 3), blk>>>(xsel, pqkv, nullptr, HD_, D_);

    seg_mem_kernel<<<B_ * H_ * 4, 256>>>(k, v, mseg, zseg);
    prefix_kernel<<<B_ * H_, 256>>>(mseg, zseg, mstate, zstate);
    attn_full_kernel<<<B_ * H_ * 16, 256, ATTN_SMEM>>>(q, k, v, mstate, zstate, betas, att);

    P3 po = {w_out, w_out, w_out, a, a, a};
    tf32gemm_kernel<false, false><<<dim3(D_ / 128, TT_ / 128, 1), blk>>>(att, po, nullptr, D_, HD_);
    P3 p1 = {w1, w1, w1, h1, h1, h1};
    tf32gemm_kernel<true, true><<<dim3(DH_ / 128, TT_ / 128, 1), blk>>>(a, p1, b1, DH_, D_);
    P3 p2 = {w2, w2, w2, h, h, h};
    tf32gemm_kernel<false, true><<<dim3(D_ / 128, TT_ / 128, 1), blk>>>(h1, p2, b2, D_, DH_);

    ln_kernel<<<B_ * S_, 256>>>(x, h, inv, ln_gamma, ln_beta, y_out, mask_out);
}